// round 4
// baseline (speedup 1.0000x reference)
#include <cuda_runtime.h>
#include <cuda_bf16.h>
#include <math.h>

// Problem constants (hardcoded from reference: x (2,64,64,256))
#define BATCH 2
#define HS 64
#define WS 64
#define C 256
#define NH 4
#define HD 64
#define LTOK 4096            // HS*WS
#define MTOK 8192            // BATCH*LTOK
#define KWIN 7
#define WSZ 49
#define SCALE 0.125f         // D^-0.5
#define MAXD 4.2426406871192851f  // sqrt(18)
#define EPS 1e-6f

// ---------------- scratch (device globals; no allocation allowed) ----------------
__device__ float g_qkv[MTOK * 768];     // silu(x@W_qkv)
__device__ float g_q[MTOK * C];         // rmsnorm+rope q
__device__ float g_k[MTOK * C];         // rmsnorm+rope k
__device__ float g_width[MTOK * NH];
__device__ float g_sharp[MTOK * NH];
__device__ float g_attn[MTOK * C];      // attention output (pre-norm)
__device__ float g_gate[MTOK * C];      // sigmoid(silu(v@W_gate + b))
__device__ float g_merged[MTOK * C];

__device__ __forceinline__ float sigmoidf_(float x) { return 1.f / (1.f + expf(-x)); }
__device__ __forceinline__ float siluf_(float x) { return x * sigmoidf_(x); }

// ---------------- tiled fp32 GEMM:  C = act(A[M,K] @ W[K,N] + bias) ----------------
// BM=BN=64, BK=16, 256 threads, 4x4 microtile. M,N,K multiples of tile sizes.
// ACT: 0 none, 1 silu, 2 sigmoid(silu(.))
template <int ACT>
__global__ void gemm_kernel(const float* __restrict__ A, int lda,
                            const float* __restrict__ W,
                            const float* __restrict__ bias,
                            float* __restrict__ Cout, int ldc,
                            int M, int N, int K) {
    __shared__ float As[16][68];
    __shared__ float Bs[16][68];
    const int tid = threadIdx.x;
    const int m0 = blockIdx.y * 64;
    const int n0 = blockIdx.x * 64;
    const int trow = (tid >> 4) * 4;
    const int tcol = (tid & 15) * 4;

    float acc[4][4] = {};

    for (int k0 = 0; k0 < K; k0 += 16) {
        #pragma unroll
        for (int r = 0; r < 4; r++) {
            int idx = tid + r * 256;
            int m = idx >> 4, kk = idx & 15;
            As[kk][m] = A[(m0 + m) * lda + k0 + kk];
        }
        #pragma unroll
        for (int r = 0; r < 4; r++) {
            int idx = tid + r * 256;
            int kk = idx >> 6, n = idx & 63;
            Bs[kk][n] = W[(k0 + kk) * N + n0 + n];
        }
        __syncthreads();
        #pragma unroll
        for (int kk = 0; kk < 16; kk++) {
            float a[4], b[4];
            #pragma unroll
            for (int i = 0; i < 4; i++) a[i] = As[kk][trow + i];
            #pragma unroll
            for (int j = 0; j < 4; j++) b[j] = Bs[kk][tcol + j];
            #pragma unroll
            for (int i = 0; i < 4; i++)
                #pragma unroll
                for (int j = 0; j < 4; j++)
                    acc[i][j] = fmaf(a[i], b[j], acc[i][j]);
        }
        __syncthreads();
    }

    #pragma unroll
    for (int i = 0; i < 4; i++) {
        #pragma unroll
        for (int j = 0; j < 4; j++) {
            float c = acc[i][j];
            if (bias) c += bias[n0 + tcol + j];
            if (ACT == 1) c = siluf_(c);
            if (ACT == 2) c = sigmoidf_(siluf_(c));
            Cout[(m0 + trow + i) * ldc + n0 + tcol + j] = c;
        }
    }
}

// ---------------- wp: width/sharpness (8 outputs/token, K=256) ----------------
__global__ void wp_kernel(const float* __restrict__ x,
                          const float* __restrict__ Wwp,
                          const float* __restrict__ bwp,
                          float* __restrict__ width,
                          float* __restrict__ sharp) {
    int tid = blockIdx.x * blockDim.x + threadIdx.x;   // MTOK*8 threads
    int t = tid >> 3, o = tid & 7;
    const float* xr = x + t * C;
    float acc = bwp[o];
    #pragma unroll 8
    for (int k = 0; k < C; k++) acc = fmaf(xr[k], Wwp[k * 8 + o], acc);
    acc = siluf_(acc);
    float s = sigmoidf_(acc);
    if (o < 4) width[t * 4 + o] = s * MAXD + 0.5f;
    else       sharp[t * 4 + (o - 4)] = s * 9.5f + 0.5f;
}

// ---------------- rmsnorm + rope for q and k (warp per token/tensor/head) ----------------
__global__ void normrope_kernel(const float* __restrict__ qkv,
                                const float* __restrict__ wq,
                                const float* __restrict__ wk,
                                float* __restrict__ qo,
                                float* __restrict__ ko) {
    int gw = (blockIdx.x * blockDim.x + threadIdx.x) >> 5;  // MTOK*8 warps
    int lane = threadIdx.x & 31;
    int t = gw >> 3;
    int rem = gw & 7;
    int tensor = rem >> 2;   // 0=q, 1=k
    int head = rem & 3;

    const float* in = qkv + t * 768 + tensor * 256 + head * 64;
    const float* w = tensor ? wk : wq;
    float v1 = in[lane], v2 = in[lane + 32];
    float ss = v1 * v1 + v2 * v2;
    #pragma unroll
    for (int o = 16; o; o >>= 1) ss += __shfl_xor_sync(0xffffffffu, ss, o);
    float inv = rsqrtf(ss * (1.f / 64.f) + EPS);
    float n1 = v1 * inv * w[lane];
    float n2 = v2 * inv * w[lane + 32];
    // rope: position index = head (per reference), freq = base^-(j/32)
    float fr = expf(-9.210340371976184f * (float)lane * (1.f / 32.f));
    float ang = (float)head * fr;
    float cs = cosf(ang), sn = sinf(ang);
    float* out = (tensor ? ko : qo) + t * 256 + head * 64;
    out[lane] = n1 * cs - n2 * sn;
    out[lane + 32] = n1 * sn + n2 * cs;
}

// ---------------- attention: warp per (token, head), two-pass over 49 ----------------
__global__ void attn_kernel(const float* __restrict__ q,
                            const float* __restrict__ k,
                            const float* __restrict__ qkv,   // v at +512, stride 768
                            const float* __restrict__ width_,
                            const float* __restrict__ sharp_,
                            float* __restrict__ out) {
    int gw = (blockIdx.x * blockDim.x + threadIdx.x) >> 5;  // MTOK*NH warps
    int lane = threadIdx.x & 31;
    int t = gw >> 2, h = gw & 3;
    int b = t >> 12, pos = t & 4095;
    int i = pos >> 6, j = pos & 63;

    const float* qp = q + t * 256 + h * 64;
    float q1 = qp[lane], q2 = qp[lane + 32];
    float wdt = width_[t * 4 + h], shp = sharp_[t * 4 + h];

    float s0 = 0.f, s1 = 0.f, m = -1e30f;
    #pragma unroll
    for (int di = -3; di <= 3; di++) {
        #pragma unroll
        for (int dj = -3; dj <= 3; dj++) {
            int w = (di + 3) * 7 + (dj + 3);
            int ii = i + di, jj = j + dj;
            bool inb = (ii >= 0) & (ii < 64) & (jj >= 0) & (jj < 64);
            float p = 0.f;
            if (inb) {
                const float* kp = k + (b * 4096 + ii * 64 + jj) * 256 + h * 64;
                p = q1 * kp[lane] + q2 * kp[lane + 32];
            }
            #pragma unroll
            for (int o = 16; o; o >>= 1) p += __shfl_xor_sync(0xffffffffu, p, o);
            float rd = sqrtf((float)(di * di + dj * dj));
            float msk = sigmoidf_((wdt - rd) * shp);
            float sc = p * SCALE - (1.f - msk) * 10000.f;
            m = fmaxf(m, sc);
            if (w < 32) { if (lane == w) s0 = sc; }
            else        { if (lane == w - 32) s1 = sc; }
        }
    }
    float p0 = expf(s0 - m);
    float p1 = (lane < WSZ - 32) ? expf(s1 - m) : 0.f;
    float sum = p0 + p1;
    #pragma unroll
    for (int o = 16; o; o >>= 1) sum += __shfl_xor_sync(0xffffffffu, sum, o);
    float inv = 1.f / sum;

    float a1 = 0.f, a2 = 0.f;
    const float* vbase = qkv + 512 + h * 64;
    #pragma unroll
    for (int di = -3; di <= 3; di++) {
        #pragma unroll
        for (int dj = -3; dj <= 3; dj++) {
            int w = (di + 3) * 7 + (dj + 3);
            int ii = i + di, jj = j + dj;
            if (ii < 0 || ii >= 64 || jj < 0 || jj >= 64) continue;
            float aw = __shfl_sync(0xffffffffu, (w < 32) ? p0 : p1, w & 31) * inv;
            const float* vp = vbase + (b * 4096 + ii * 64 + jj) * 768;
            a1 = fmaf(aw, vp[lane], a1);
            a2 = fmaf(aw, vp[lane + 32], a2);
        }
    }
    float* op = out + t * 256 + h * 64;
    op[lane] = a1;
    op[lane + 32] = a2;
}

// ---------------- merge: rmsnorm(attn)*w_onorm, gate blend (warp per token) ----------------
__global__ void merge_kernel(const float* __restrict__ attn,
                             const float* __restrict__ qkv,     // v at +512
                             const float* __restrict__ gate,
                             const float* __restrict__ won,
                             float* __restrict__ merged) {
    int gw = (blockIdx.x * blockDim.x + threadIdx.x) >> 5;  // MTOK warps
    int lane = threadIdx.x & 31;
    const float* ap = attn + gw * 256;
    float a[8];
    float ss = 0.f;
    #pragma unroll
    for (int u = 0; u < 8; u++) {
        a[u] = ap[lane + u * 32];
        ss = fmaf(a[u], a[u], ss);
    }
    #pragma unroll
    for (int o = 16; o; o >>= 1) ss += __shfl_xor_sync(0xffffffffu, ss, o);
    float inv = rsqrtf(ss * (1.f / 256.f) + EPS);
    const float* vp = qkv + gw * 768 + 512;
    const float* gp = gate + gw * 256;
    float* mp = merged + gw * 256;
    #pragma unroll
    for (int u = 0; u < 8; u++) {
        int c = lane + u * 32;
        float onorm = a[u] * inv * won[c];
        float g = gp[c];
        float v = vp[c];
        mp[c] = g * v + (1.f - g) * onorm;
    }
}

extern "C" void kernel_launch(void* const* d_in, const int* in_sizes, int n_in,
                              void* d_out, int out_size) {
    const float* x       = (const float*)d_in[0];
    const float* W_qkv   = (const float*)d_in[1];
    const float* w_qnorm = (const float*)d_in[2];
    const float* w_knorm = (const float*)d_in[3];
    const float* W_wp    = (const float*)d_in[4];
    const float* b_wp    = (const float*)d_in[5];
    const float* w_onorm = (const float*)d_in[6];
    const float* W_out   = (const float*)d_in[7];
    const float* W_gate  = (const float*)d_in[8];
    const float* b_gate  = (const float*)d_in[9];
    float* out = (float*)d_out;

    float *qkv, *qb, *kb, *wid, *shp, *att, *gat, *mrg;
    cudaGetSymbolAddress((void**)&qkv, g_qkv);
    cudaGetSymbolAddress((void**)&qb,  g_q);
    cudaGetSymbolAddress((void**)&kb,  g_k);
    cudaGetSymbolAddress((void**)&wid, g_width);
    cudaGetSymbolAddress((void**)&shp, g_sharp);
    cudaGetSymbolAddress((void**)&att, g_attn);
    cudaGetSymbolAddress((void**)&gat, g_gate);
    cudaGetSymbolAddress((void**)&mrg, g_merged);

    // 1. qkv = silu(x @ W_qkv)
    gemm_kernel<1><<<dim3(768 / 64, MTOK / 64), 256>>>(x, C, W_qkv, nullptr, qkv, 768,
                                                       MTOK, 768, C);
    // 2. width / sharpness
    wp_kernel<<<(MTOK * 8) / 256, 256>>>(x, W_wp, b_wp, wid, shp);
    // 3. rmsnorm + rope (q and k)
    normrope_kernel<<<(MTOK * 8 * 32) / 256, 256>>>(qkv, w_qnorm, w_knorm, qb, kb);
    // 4. gate = sigmoid(silu(v @ W_gate + b_gate))
    gemm_kernel<2><<<dim3(256 / 64, MTOK / 64), 256>>>(qkv + 512, 768, W_gate, b_gate,
                                                       gat, 256, MTOK, 256, C);
    // 5. local attention
    attn_kernel<<<(MTOK * NH * 32) / 256, 256>>>(qb, kb, qkv, wid, shp, att);
    // 6. merge (rmsnorm + gated blend)
    merge_kernel<<<(MTOK * 32) / 256, 256>>>(att, qkv, gat, w_onorm, mrg);
    // 7. out = silu(merged @ W_out)
    gemm_kernel<1><<<dim3(256 / 64, MTOK / 64), 256>>>(mrg, 256, W_out, nullptr, out, 256,
                                                       MTOK, 256, C);
}

// round 5
// speedup vs baseline: 1.4176x; 1.4176x over previous
#include <cuda_runtime.h>
#include <cuda_bf16.h>
#include <math.h>

// Problem constants (x: (2,64,64,256))
#define BATCH 2
#define C 256
#define NH 4
#define MTOK 8192
#define WSZ 49
#define SCALE 0.125f
#define MAXD 4.2426406871192851f
#define EPS 1e-6f

// ---------------- scratch ----------------
__device__ float g_qkv[MTOK * 768];
__device__ float g_q[MTOK * C];
__device__ float g_k[MTOK * C];
__device__ float g_width[MTOK * NH];
__device__ float g_sharp[MTOK * NH];
__device__ float g_attn[MTOK * C];
__device__ float g_gate[MTOK * C];
__device__ float g_merged[MTOK * C];

__device__ __forceinline__ float fsig(float x) {
    return __fdividef(1.f, 1.f + __expf(-x));
}
__device__ __forceinline__ float fsilu(float x) { return x * fsig(x); }

// ---------------- 128x128x16 fp32 GEMM, 8x8 microtile ----------------
// ACT: 0 none, 1 silu, 2 sigmoid(silu)
template <int ACT>
__global__ __launch_bounds__(256, 2)
void gemm128(const float* __restrict__ A, int lda,
             const float* __restrict__ W, int ldw,
             const float* __restrict__ bias,
             float* __restrict__ Cout, int ldc, int K) {
    __shared__ float As[16][132];
    __shared__ float Bs[16][128];
    const int tid = threadIdx.x;
    const int tx = tid & 15, ty = tid >> 4;
    const int m0 = blockIdx.y * 128, n0 = blockIdx.x * 128;

    // A loader: f0=tid -> row=tid>>2, kq=(tid&3)*4 ; f1=tid+256 -> row+64
    const int arow = tid >> 2;
    const int ak = (tid & 3) << 2;
    const float* Ap0 = A + (m0 + arow) * lda + ak;
    const float* Ap1 = Ap0 + 64 * lda;
    // B loader: f0=tid -> kk=tid>>5, n4=(tid&31)*4 ; f1 -> kk+8
    const int bkk = tid >> 5;
    const int bn = (tid & 31) << 2;
    const float* Bp0 = W + bkk * ldw + n0 + bn;
    const float* Bp1 = Bp0 + 8 * ldw;

    float acc[8][8] = {};
    float4 pa0, pa1, pb0, pb1;

    // prime tile 0
    pa0 = *(const float4*)(Ap0);
    pa1 = *(const float4*)(Ap1);
    pb0 = *(const float4*)(Bp0);
    pb1 = *(const float4*)(Bp1);
    {
        As[ak + 0][arow] = pa0.x; As[ak + 1][arow] = pa0.y;
        As[ak + 2][arow] = pa0.z; As[ak + 3][arow] = pa0.w;
        As[ak + 0][arow + 64] = pa1.x; As[ak + 1][arow + 64] = pa1.y;
        As[ak + 2][arow + 64] = pa1.z; As[ak + 3][arow + 64] = pa1.w;
        *(float4*)&Bs[bkk][bn] = pb0;
        *(float4*)&Bs[bkk + 8][bn] = pb1;
    }
    __syncthreads();

    const int NT = K >> 4;
    for (int kt = 0; kt < NT; kt++) {
        if (kt + 1 < NT) {
            int ko = (kt + 1) << 4;
            pa0 = *(const float4*)(Ap0 + ko);
            pa1 = *(const float4*)(Ap1 + ko);
            pb0 = *(const float4*)(Bp0 + ko * ldw);
            pb1 = *(const float4*)(Bp1 + ko * ldw);
        }
        #pragma unroll
        for (int kk = 0; kk < 16; kk++) {
            float a[8], b[8];
            float4 t0 = *(const float4*)&As[kk][ty << 2];
            float4 t1 = *(const float4*)&As[kk][(ty << 2) + 64];
            float4 t2 = *(const float4*)&Bs[kk][tx << 2];
            float4 t3 = *(const float4*)&Bs[kk][(tx << 2) + 64];
            a[0]=t0.x; a[1]=t0.y; a[2]=t0.z; a[3]=t0.w;
            a[4]=t1.x; a[5]=t1.y; a[6]=t1.z; a[7]=t1.w;
            b[0]=t2.x; b[1]=t2.y; b[2]=t2.z; b[3]=t2.w;
            b[4]=t3.x; b[5]=t3.y; b[6]=t3.z; b[7]=t3.w;
            #pragma unroll
            for (int i = 0; i < 8; i++)
                #pragma unroll
                for (int j = 0; j < 8; j++)
                    acc[i][j] = fmaf(a[i], b[j], acc[i][j]);
        }
        __syncthreads();
        if (kt + 1 < NT) {
            As[ak + 0][arow] = pa0.x; As[ak + 1][arow] = pa0.y;
            As[ak + 2][arow] = pa0.z; As[ak + 3][arow] = pa0.w;
            As[ak + 0][arow + 64] = pa1.x; As[ak + 1][arow + 64] = pa1.y;
            As[ak + 2][arow + 64] = pa1.z; As[ak + 3][arow + 64] = pa1.w;
            *(float4*)&Bs[bkk][bn] = pb0;
            *(float4*)&Bs[bkk + 8][bn] = pb1;
            __syncthreads();
        }
    }

    // epilogue
    #pragma unroll
    for (int i = 0; i < 8; i++) {
        int r = m0 + (ty << 2) + ((i < 4) ? i : 60 + i);
        #pragma unroll
        for (int g = 0; g < 2; g++) {
            int cbase = n0 + (tx << 2) + g * 64;
            float4 o;
            float e[4];
            #pragma unroll
            for (int j = 0; j < 4; j++) {
                float cv = acc[i][g * 4 + j];
                if (bias) cv += bias[cbase + j];
                if (ACT == 1) cv = fsilu(cv);
                if (ACT == 2) cv = fsig(fsilu(cv));
                e[j] = cv;
            }
            o.x = e[0]; o.y = e[1]; o.z = e[2]; o.w = e[3];
            *(float4*)&Cout[r * ldc + cbase] = o;
        }
    }
}

// ---------------- wp: width/sharpness ----------------
__global__ void wp_kernel(const float* __restrict__ x,
                          const float* __restrict__ Wwp,
                          const float* __restrict__ bwp,
                          float* __restrict__ width,
                          float* __restrict__ sharp) {
    __shared__ float ws[C * 8];
    int tid = threadIdx.x;
    #pragma unroll
    for (int r = 0; r < 8; r++) ws[tid + r * 256] = Wwp[tid + r * 256];
    __syncthreads();
    int gid = blockIdx.x * blockDim.x + tid;   // MTOK*8 threads
    int t = gid >> 3, o = gid & 7;
    const float4* x4 = (const float4*)(x + t * C);
    float acc = bwp[o];
    #pragma unroll 16
    for (int k4 = 0; k4 < 64; k4++) {
        float4 xv = x4[k4];
        int kb = (k4 << 2) * 8 + o;
        acc = fmaf(xv.x, ws[kb], acc);
        acc = fmaf(xv.y, ws[kb + 8], acc);
        acc = fmaf(xv.z, ws[kb + 16], acc);
        acc = fmaf(xv.w, ws[kb + 24], acc);
    }
    acc = fsilu(acc);
    float s = fsig(acc);
    if (o < 4) width[t * 4 + o] = s * MAXD + 0.5f;
    else       sharp[t * 4 + (o - 4)] = s * 9.5f + 0.5f;
}

// ---------------- rmsnorm + rope (warp per token/tensor/head) ----------------
__global__ void normrope_kernel(const float* __restrict__ qkv,
                                const float* __restrict__ wq,
                                const float* __restrict__ wk,
                                float* __restrict__ qo,
                                float* __restrict__ ko) {
    int gw = (blockIdx.x * blockDim.x + threadIdx.x) >> 5;
    int lane = threadIdx.x & 31;
    int t = gw >> 3;
    int rem = gw & 7;
    int tensor = rem >> 2;
    int head = rem & 3;

    const float* in = qkv + t * 768 + tensor * 256 + head * 64;
    const float* w = tensor ? wk : wq;
    float v1 = in[lane], v2 = in[lane + 32];
    float ss = v1 * v1 + v2 * v2;
    #pragma unroll
    for (int o = 16; o; o >>= 1) ss += __shfl_xor_sync(0xffffffffu, ss, o);
    float inv = rsqrtf(ss * (1.f / 64.f) + EPS);
    float n1 = v1 * inv * w[lane];
    float n2 = v2 * inv * w[lane + 32];
    float fr = __expf(-9.210340371976184f * (float)lane * (1.f / 32.f));
    float ang = (float)head * fr;
    float cs = __cosf(ang), sn = __sinf(ang);
    float* out = (tensor ? ko : qo) + t * 256 + head * 64;
    out[lane] = n1 * cs - n2 * sn;
    out[lane + 32] = n1 * sn + n2 * cs;
}

// ---------------- attention: single-pass online softmax ----------------
__global__ void attn_kernel(const float* __restrict__ q,
                            const float* __restrict__ k,
                            const float* __restrict__ qkv,
                            const float* __restrict__ width_,
                            const float* __restrict__ sharp_,
                            float* __restrict__ out) {
    int gw = (blockIdx.x * blockDim.x + threadIdx.x) >> 5;
    int lane = threadIdx.x & 31;
    int t = gw >> 2, h = gw & 3;
    int i = (t >> 6) & 63, j = t & 63;

    const float* qp = q + t * 256 + h * 64;
    const float* kc = k + t * 256 + h * 64;
    const float* vc = qkv + t * 768 + 512 + h * 64;
    float q1 = qp[lane], q2 = qp[lane + 32];
    float wdt = width_[t * 4 + h], shp = sharp_[t * 4 + h];

    float m = -1e30f, sum = 0.f, a1 = 0.f, a2 = 0.f;
    #pragma unroll
    for (int di = -3; di <= 3; di++) {
        #pragma unroll
        for (int dj = -3; dj <= 3; dj++) {
            const float rd = sqrtf((float)(di * di + dj * dj));  // compile-time
            int ii = i + di, jj = j + dj;
            bool inb = ((unsigned)ii < 64u) & ((unsigned)jj < 64u);
            int off = di * 64 + dj;
            const float* kp = kc + off * 256;
            const float* vp = vc + off * 768;
            float p = 0.f;
            if (inb) p = q1 * kp[lane] + q2 * kp[lane + 32];
            #pragma unroll
            for (int o = 16; o; o >>= 1) p += __shfl_xor_sync(0xffffffffu, p, o);
            float msk = fsig((wdt - rd) * shp);
            float sc = fmaf(p, SCALE, -(1.f - msk) * 10000.f);
            if (sc > m) {            // warp-uniform branch
                float corr = __expf(m - sc);
                sum *= corr; a1 *= corr; a2 *= corr;
                m = sc;
            }
            float wgt = __expf(sc - m);
            sum += wgt;
            if (inb) {
                a1 = fmaf(wgt, vp[lane], a1);
                a2 = fmaf(wgt, vp[lane + 32], a2);
            }
        }
    }
    float inv = __fdividef(1.f, sum);
    float* op = out + t * 256 + h * 64;
    op[lane] = a1 * inv;
    op[lane + 32] = a2 * inv;
}

// ---------------- merge: rmsnorm(attn) + gated blend ----------------
__global__ void merge_kernel(const float* __restrict__ attn,
                             const float* __restrict__ qkv,
                             const float* __restrict__ gate,
                             const float* __restrict__ won,
                             float* __restrict__ merged) {
    int gw = (blockIdx.x * blockDim.x + threadIdx.x) >> 5;
    int lane = threadIdx.x & 31;
    const float* ap = attn + gw * 256;
    float a[8];
    float ss = 0.f;
    #pragma unroll
    for (int u = 0; u < 8; u++) {
        a[u] = ap[lane + u * 32];
        ss = fmaf(a[u], a[u], ss);
    }
    #pragma unroll
    for (int o = 16; o; o >>= 1) ss += __shfl_xor_sync(0xffffffffu, ss, o);
    float inv = rsqrtf(ss * (1.f / 256.f) + EPS);
    const float* vp = qkv + gw * 768 + 512;
    const float* gp = gate + gw * 256;
    float* mp = merged + gw * 256;
    #pragma unroll
    for (int u = 0; u < 8; u++) {
        int c = lane + u * 32;
        float onorm = a[u] * inv * won[c];
        float g = gp[c];
        float v = vp[c];
        mp[c] = g * v + (1.f - g) * onorm;
    }
}

extern "C" void kernel_launch(void* const* d_in, const int* in_sizes, int n_in,
                              void* d_out, int out_size) {
    const float* x       = (const float*)d_in[0];
    const float* W_qkv   = (const float*)d_in[1];
    const float* w_qnorm = (const float*)d_in[2];
    const float* w_knorm = (const float*)d_in[3];
    const float* W_wp    = (const float*)d_in[4];
    const float* b_wp    = (const float*)d_in[5];
    const float* w_onorm = (const float*)d_in[6];
    const float* W_out   = (const float*)d_in[7];
    const float* W_gate  = (const float*)d_in[8];
    const float* b_gate  = (const float*)d_in[9];
    float* out = (float*)d_out;

    float *qkv, *qb, *kb, *wid, *shp, *att, *gat, *mrg;
    cudaGetSymbolAddress((void**)&qkv, g_qkv);
    cudaGetSymbolAddress((void**)&qb,  g_q);
    cudaGetSymbolAddress((void**)&kb,  g_k);
    cudaGetSymbolAddress((void**)&wid, g_width);
    cudaGetSymbolAddress((void**)&shp, g_sharp);
    cudaGetSymbolAddress((void**)&att, g_attn);
    cudaGetSymbolAddress((void**)&gat, g_gate);
    cudaGetSymbolAddress((void**)&mrg, g_merged);

    // 1. qkv = silu(x @ W_qkv)
    gemm128<1><<<dim3(768 / 128, MTOK / 128), 256>>>(x, C, W_qkv, 768, nullptr,
                                                     qkv, 768, C);
    // 2. width / sharpness
    wp_kernel<<<(MTOK * 8) / 256, 256>>>(x, W_wp, b_wp, wid, shp);
    // 3. rmsnorm + rope
    normrope_kernel<<<(MTOK * 8 * 32) / 256, 256>>>(qkv, w_qnorm, w_knorm, qb, kb);
    // 4. gate = sigmoid(silu(v @ W_gate + b_gate))
    gemm128<2><<<dim3(256 / 128, MTOK / 128), 256>>>(qkv + 512, 768, W_gate, 256,
                                                     b_gate, gat, 256, C);
    // 5. local attention (online softmax, single pass)
    attn_kernel<<<(MTOK * NH * 32) / 256, 256>>>(qb, kb, qkv, wid, shp, att);
    // 6. merge
    merge_kernel<<<(MTOK * 32) / 256, 256>>>(att, qkv, gat, w_onorm, mrg);
    // 7. out = silu(merged @ W_out)
    gemm128<1><<<dim3(256 / 128, MTOK / 128), 256>>>(mrg, 256, W_out, 256, nullptr,
                                                     out, 256, C);
}